// round 2
// baseline (speedup 1.0000x reference)
#include <cuda_runtime.h>

#define B_  4
#define S_  2048
#define D_  1024
#define H_  16
#define DK_ 64

// Scratch (allocation rules forbid cudaMalloc; __device__ globals are the
// sanctioned workaround). 4 x 32 MB.
__device__ float g_Q[(size_t)B_ * S_ * D_];
__device__ float g_K[(size_t)B_ * S_ * D_];
__device__ float g_V[(size_t)B_ * S_ * D_];
__device__ float g_A[(size_t)B_ * S_ * D_];

// ---------------------------------------------------------------------------
// GEMM: C[M,N] = A[M,K] * B[N,K]^T   (torch Linear: y = x @ W.T, W is [out,in])
// BM=BN=128, BK=16, 256 threads, 8x8 microtile per thread.
// ---------------------------------------------------------------------------
__global__ void __launch_bounds__(256)
gemm_atb_kernel(const float* __restrict__ A, const float* __restrict__ Bm,
                float* __restrict__ C, int M, int N, int Kd)
{
    __shared__ float As[16][132];   // +4 pad: kills 4-way conflicts on transposed stores
    __shared__ float Bs[16][132];

    const int tid = threadIdx.x;
    const int m0  = blockIdx.y * 128;
    const int n0  = blockIdx.x * 128;
    const int tx  = tid & 15;
    const int ty  = tid >> 4;

    float acc[8][8];
    #pragma unroll
    for (int i = 0; i < 8; i++)
        #pragma unroll
        for (int j = 0; j < 8; j++) acc[i][j] = 0.f;

    for (int k0 = 0; k0 < Kd; k0 += 16) {
        #pragma unroll
        for (int i = 0; i < 2; i++) {
            int idx = tid + i * 256;        // 0..511
            int row = idx >> 2;             // 0..127
            int kc  = (idx & 3) << 2;       // 0,4,8,12
            float4 va = *reinterpret_cast<const float4*>(
                A + (size_t)(m0 + row) * Kd + k0 + kc);
            As[kc + 0][row] = va.x; As[kc + 1][row] = va.y;
            As[kc + 2][row] = va.z; As[kc + 3][row] = va.w;
            float4 vb = *reinterpret_cast<const float4*>(
                Bm + (size_t)(n0 + row) * Kd + k0 + kc);
            Bs[kc + 0][row] = vb.x; Bs[kc + 1][row] = vb.y;
            Bs[kc + 2][row] = vb.z; Bs[kc + 3][row] = vb.w;
        }
        __syncthreads();

        #pragma unroll
        for (int kk = 0; kk < 16; kk++) {
            float4 a0 = *reinterpret_cast<const float4*>(&As[kk][ty * 8]);
            float4 a1 = *reinterpret_cast<const float4*>(&As[kk][ty * 8 + 4]);
            float4 b0 = *reinterpret_cast<const float4*>(&Bs[kk][tx * 8]);
            float4 b1 = *reinterpret_cast<const float4*>(&Bs[kk][tx * 8 + 4]);
            float a[8] = {a0.x, a0.y, a0.z, a0.w, a1.x, a1.y, a1.z, a1.w};
            float b[8] = {b0.x, b0.y, b0.z, b0.w, b1.x, b1.y, b1.z, b1.w};
            #pragma unroll
            for (int i = 0; i < 8; i++)
                #pragma unroll
                for (int j = 0; j < 8; j++)
                    acc[i][j] = fmaf(a[i], b[j], acc[i][j]);
        }
        __syncthreads();
    }

    #pragma unroll
    for (int i = 0; i < 8; i++) {
        float* cp = C + (size_t)(m0 + ty * 8 + i) * N + n0 + tx * 8;
        *reinterpret_cast<float4*>(cp) =
            make_float4(acc[i][0], acc[i][1], acc[i][2], acc[i][3]);
        *reinterpret_cast<float4*>(cp + 4) =
            make_float4(acc[i][4], acc[i][5], acc[i][6], acc[i][7]);
    }
}

// ---------------------------------------------------------------------------
// Flash-style attention over projected Q/K/V kept in [B,S,D] layout
// (head h occupies cols h*64..h*64+63). One thread = one query row.
// Block: 128 threads = 128 query rows. Grid: (S/128, B*H).
// Key/value tiles of 64 rows staged in smem (32 KB static).
// ---------------------------------------------------------------------------
__global__ void __launch_bounds__(128)
attn_kernel(const float* __restrict__ Q, const float* __restrict__ Kt,
            const float* __restrict__ Vt, const int* __restrict__ mask,
            float* __restrict__ O)
{
    __shared__ float4 Ks[64 * 16];   // 64 keys x 64 floats
    __shared__ float4 Vs[64 * 16];

    const int tid  = threadIdx.x;
    const int b    = blockIdx.y >> 4;
    const int h    = blockIdx.y & 15;
    const int qrow = blockIdx.x * 128 + tid;

    const size_t qoff = ((size_t)b * S_ + qrow) * D_ + h * DK_;
    const float4* qp = reinterpret_cast<const float4*>(Q + qoff);
    float4 qr[16];
    #pragma unroll
    for (int i = 0; i < 16; i++) qr[i] = qp[i];

    float4 o[16];
    #pragma unroll
    for (int i = 0; i < 16; i++) o[i] = make_float4(0.f, 0.f, 0.f, 0.f);
    float mrun = -1e30f, lrun = 0.f;

    const int* mrow = mask + ((size_t)b * S_ + qrow) * S_;

    for (int kt = 0; kt < S_; kt += 64) {
        __syncthreads();
        #pragma unroll
        for (int i = 0; i < 8; i++) {
            int idx = tid + i * 128;        // 0..1023
            int r = idx >> 4;               // key row 0..63
            int c = idx & 15;               // float4 col
            size_t goff = ((size_t)b * S_ + kt + r) * D_ + h * DK_ + c * 4;
            Ks[idx] = *reinterpret_cast<const float4*>(Kt + goff);
            Vs[idx] = *reinterpret_cast<const float4*>(Vt + goff);
        }
        __syncthreads();

        #pragma unroll
        for (int cch = 0; cch < 2; cch++) {
            float s[32];
            // scores: all smem reads warp-uniform -> broadcast, conflict-free
            #pragma unroll
            for (int j = 0; j < 32; j++) {
                const float4* kr = &Ks[(cch * 32 + j) * 16];
                float acc = 0.f;
                #pragma unroll
                for (int d = 0; d < 16; d++) {
                    float4 kv = kr[d];
                    acc = fmaf(qr[d].x, kv.x, acc);
                    acc = fmaf(qr[d].y, kv.y, acc);
                    acc = fmaf(qr[d].z, kv.z, acc);
                    acc = fmaf(qr[d].w, kv.w, acc);
                }
                s[j] = acc * 0.125f;        // 1/sqrt(64)
            }
            // mask (int4-vectorized, short-lived regs)
            #pragma unroll
            for (int i = 0; i < 8; i++) {
                int4 mm = *reinterpret_cast<const int4*>(mrow + kt + cch * 32 + i * 4);
                if (mm.x == 0) s[i * 4 + 0] = -1e9f;
                if (mm.y == 0) s[i * 4 + 1] = -1e9f;
                if (mm.z == 0) s[i * 4 + 2] = -1e9f;
                if (mm.w == 0) s[i * 4 + 3] = -1e9f;
            }
            // online softmax update
            float cmax = s[0];
            #pragma unroll
            for (int j = 1; j < 32; j++) cmax = fmaxf(cmax, s[j]);
            float mnew = fmaxf(mrun, cmax);
            float corr = __expf(mrun - mnew);
            lrun *= corr;
            #pragma unroll
            for (int i = 0; i < 16; i++) {
                o[i].x *= corr; o[i].y *= corr; o[i].z *= corr; o[i].w *= corr;
            }
            mrun = mnew;
            #pragma unroll
            for (int j = 0; j < 32; j++) {
                float p = __expf(s[j] - mrun);
                lrun += p;
                const float4* vr = &Vs[(cch * 32 + j) * 16];
                #pragma unroll
                for (int d = 0; d < 16; d++) {
                    float4 vv = vr[d];
                    o[d].x = fmaf(p, vv.x, o[d].x);
                    o[d].y = fmaf(p, vv.y, o[d].y);
                    o[d].z = fmaf(p, vv.z, o[d].z);
                    o[d].w = fmaf(p, vv.w, o[d].w);
                }
            }
        }
    }

    float inv = 1.f / lrun;
    float* op = O + ((size_t)b * S_ + qrow) * D_ + h * DK_;
    #pragma unroll
    for (int i = 0; i < 16; i++) {
        reinterpret_cast<float4*>(op)[i] =
            make_float4(o[i].x * inv, o[i].y * inv, o[i].z * inv, o[i].w * inv);
    }
}

// ---------------------------------------------------------------------------
// Launch: 5 kernels, graph-capturable, no allocations / syncs.
// Input order per metadata: q, k, v, mask, w_q, w_k, w_v, w_o. Output fp32.
// ---------------------------------------------------------------------------
extern "C" void kernel_launch(void* const* d_in, const int* in_sizes, int n_in,
                              void* d_out, int out_size)
{
    const float* q    = (const float*)d_in[0];
    const float* k    = (const float*)d_in[1];
    const float* v    = (const float*)d_in[2];
    const int*   mask = (const int*)  d_in[3];
    const float* w_q  = (const float*)d_in[4];
    const float* w_k  = (const float*)d_in[5];
    const float* w_v  = (const float*)d_in[6];
    const float* w_o  = (const float*)d_in[7];
    float* out = (float*)d_out;

    float *gq, *gk, *gv, *ga;
    cudaGetSymbolAddress((void**)&gq, g_Q);
    cudaGetSymbolAddress((void**)&gk, g_K);
    cudaGetSymbolAddress((void**)&gv, g_V);
    cudaGetSymbolAddress((void**)&ga, g_A);

    const int M = B_ * S_;                 // 8192
    dim3 gemm_grid(D_ / 128, M / 128);     // (8, 64)

    gemm_atb_kernel<<<gemm_grid, 256>>>(q, w_q, gq, M, D_, D_);
    gemm_atb_kernel<<<gemm_grid, 256>>>(k, w_k, gk, M, D_, D_);
    gemm_atb_kernel<<<gemm_grid, 256>>>(v, w_v, gv, M, D_, D_);

    dim3 attn_grid(S_ / 128, B_ * H_);     // (16, 64)
    attn_kernel<<<attn_grid, 128>>>(gq, gk, gv, mask, ga);

    gemm_atb_kernel<<<gemm_grid, 256>>>(ga, w_o, out, M, D_, D_);
}

// round 4
// speedup vs baseline: 1.0727x; 1.0727x over previous
#include <cuda_runtime.h>

#define B_  4
#define S_  2048
#define D_  1024
#define H_  16
#define DK_ 64

// Scratch (allocation rules forbid cudaMalloc; __device__ globals are the
// sanctioned workaround). 4 x 32 MB.
__device__ float g_Q[(size_t)B_ * S_ * D_];
__device__ float g_K[(size_t)B_ * S_ * D_];
__device__ float g_V[(size_t)B_ * S_ * D_];
__device__ float g_A[(size_t)B_ * S_ * D_];

// ---------------------------------------------------------------------------
// GEMM: C[M,N] = A[M,K] * B[N,K]^T   (torch Linear: y = x @ W.T, W is [out,in])
// BM=BN=128, BK=16, 256 threads, 8x8 microtile per thread.
// ---------------------------------------------------------------------------
__global__ void __launch_bounds__(256)
gemm_atb_kernel(const float* __restrict__ A, const float* __restrict__ Bm,
                float* __restrict__ C, int M, int N, int Kd)
{
    __shared__ float As[16][132];
    __shared__ float Bs[16][132];

    const int tid = threadIdx.x;
    const int m0  = blockIdx.y * 128;
    const int n0  = blockIdx.x * 128;
    const int tx  = tid & 15;
    const int ty  = tid >> 4;

    float acc[8][8];
    #pragma unroll
    for (int i = 0; i < 8; i++)
        #pragma unroll
        for (int j = 0; j < 8; j++) acc[i][j] = 0.f;

    for (int k0 = 0; k0 < Kd; k0 += 16) {
        #pragma unroll
        for (int i = 0; i < 2; i++) {
            int idx = tid + i * 256;
            int row = idx >> 2;
            int kc  = (idx & 3) << 2;
            float4 va = *reinterpret_cast<const float4*>(
                A + (size_t)(m0 + row) * Kd + k0 + kc);
            As[kc + 0][row] = va.x; As[kc + 1][row] = va.y;
            As[kc + 2][row] = va.z; As[kc + 3][row] = va.w;
            float4 vb = *reinterpret_cast<const float4*>(
                Bm + (size_t)(n0 + row) * Kd + k0 + kc);
            Bs[kc + 0][row] = vb.x; Bs[kc + 1][row] = vb.y;
            Bs[kc + 2][row] = vb.z; Bs[kc + 3][row] = vb.w;
        }
        __syncthreads();

        #pragma unroll
        for (int kk = 0; kk < 16; kk++) {
            float4 a0 = *reinterpret_cast<const float4*>(&As[kk][ty * 8]);
            float4 a1 = *reinterpret_cast<const float4*>(&As[kk][ty * 8 + 4]);
            float4 b0 = *reinterpret_cast<const float4*>(&Bs[kk][tx * 8]);
            float4 b1 = *reinterpret_cast<const float4*>(&Bs[kk][tx * 8 + 4]);
            float a[8] = {a0.x, a0.y, a0.z, a0.w, a1.x, a1.y, a1.z, a1.w};
            float b[8] = {b0.x, b0.y, b0.z, b0.w, b1.x, b1.y, b1.z, b1.w};
            #pragma unroll
            for (int i = 0; i < 8; i++)
                #pragma unroll
                for (int j = 0; j < 8; j++)
                    acc[i][j] = fmaf(a[i], b[j], acc[i][j]);
        }
        __syncthreads();
    }

    #pragma unroll
    for (int i = 0; i < 8; i++) {
        float* cp = C + (size_t)(m0 + ty * 8 + i) * N + n0 + tx * 8;
        *reinterpret_cast<float4*>(cp) =
            make_float4(acc[i][0], acc[i][1], acc[i][2], acc[i][3]);
        *reinterpret_cast<float4*>(cp + 4) =
            make_float4(acc[i][4], acc[i][5], acc[i][6], acc[i][7]);
    }
}

// ---------------------------------------------------------------------------
// Flash-style attention, partner-split over d_k.
// 256 threads/block: thread pair (2q, 2q+1) handles query row q's two 32-dim
// halves. Per-thread state: qr 8xfloat4, o 8xfloat4, s[32]  (~120 regs ->
// 2 CTAs/SM = 16 warps, vs 251 regs / 8 warps before).
// Score = own 32-dim partial + __shfl_xor(partner partial, 1); both partners
// then run identical (bit-exact) softmax bookkeeping.
// Grid: (S/128, B*H).
// ---------------------------------------------------------------------------
__global__ void __launch_bounds__(256, 2)
attn_kernel(const float* __restrict__ Q, const float* __restrict__ Kt,
            const float* __restrict__ Vt, const int* __restrict__ mask,
            float* __restrict__ O)
{
    __shared__ float4 Ks[64 * 16];   // 64 keys x 64 floats (16 KB)
    __shared__ float4 Vs[64 * 16];   // 16 KB

    const int tid  = threadIdx.x;          // 0..255
    const int qi   = tid >> 1;             // local query row 0..127
    const int hd   = tid & 1;              // which 32-dim half
    const int b    = blockIdx.y >> 4;
    const int h    = blockIdx.y & 15;
    const int qrow = blockIdx.x * 128 + qi;

    const size_t base = ((size_t)b * S_ + qrow) * D_ + h * DK_ + hd * 32;
    const float4* qp = reinterpret_cast<const float4*>(Q + base);
    float4 qr[8];
    #pragma unroll
    for (int i = 0; i < 8; i++) qr[i] = qp[i];

    float4 o[8];
    #pragma unroll
    for (int i = 0; i < 8; i++) o[i] = make_float4(0.f, 0.f, 0.f, 0.f);
    float mrun = -1e30f, lrun = 0.f;

    const int* mrow = mask + ((size_t)b * S_ + qrow) * S_;

    for (int kt = 0; kt < S_; kt += 64) {
        __syncthreads();
        // stage 64x64 K and V tiles: 1024 float4 each, 256 threads -> 4 apiece
        #pragma unroll
        for (int i = 0; i < 4; i++) {
            int idx = tid + i * 256;        // 0..1023
            int r = idx >> 4;               // key row 0..63
            int c = idx & 15;               // float4 col
            size_t goff = ((size_t)b * S_ + kt + r) * D_ + h * DK_ + c * 4;
            Ks[idx] = *reinterpret_cast<const float4*>(Kt + goff);
            Vs[idx] = *reinterpret_cast<const float4*>(Vt + goff);
        }
        __syncthreads();

        #pragma unroll
        for (int cch = 0; cch < 2; cch++) {
            float s[32];
            // partial scores over this thread's 32 dims (8 float4)
            #pragma unroll
            for (int j = 0; j < 32; j++) {
                const float4* kr = &Ks[(cch * 32 + j) * 16 + hd * 8];
                float acc = 0.f;
                #pragma unroll
                for (int d = 0; d < 8; d++) {
                    float4 kv = kr[d];
                    acc = fmaf(qr[d].x, kv.x, acc);
                    acc = fmaf(qr[d].y, kv.y, acc);
                    acc = fmaf(qr[d].z, kv.z, acc);
                    acc = fmaf(qr[d].w, kv.w, acc);
                }
                s[j] = acc;
            }
            // combine partner halves (a+b commutative -> bit-identical in both)
            #pragma unroll
            for (int j = 0; j < 32; j++)
                s[j] = (s[j] + __shfl_xor_sync(0xffffffffu, s[j], 1)) * 0.125f;

            // mask (partner lanes hit same addr -> broadcast)
            #pragma unroll
            for (int i = 0; i < 8; i++) {
                int4 mm = *reinterpret_cast<const int4*>(mrow + kt + cch * 32 + i * 4);
                if (mm.x == 0) s[i * 4 + 0] = -1e9f;
                if (mm.y == 0) s[i * 4 + 1] = -1e9f;
                if (mm.z == 0) s[i * 4 + 2] = -1e9f;
                if (mm.w == 0) s[i * 4 + 3] = -1e9f;
            }

            // online softmax update
            float cmax = s[0];
            #pragma unroll
            for (int j = 1; j < 32; j++) cmax = fmaxf(cmax, s[j]);
            float mnew = fmaxf(mrun, cmax);
            float corr = __expf(mrun - mnew);
            lrun *= corr;
            #pragma unroll
            for (int i = 0; i < 8; i++) {
                o[i].x *= corr; o[i].y *= corr; o[i].z *= corr; o[i].w *= corr;
            }
            mrun = mnew;
            #pragma unroll
            for (int j = 0; j < 32; j++) {
                float p = __expf(s[j] - mrun);
                lrun += p;
                const float4* vr = &Vs[(cch * 32 + j) * 16 + hd * 8];
                #pragma unroll
                for (int d = 0; d < 8; d++) {
                    float4 vv = vr[d];
                    o[d].x = fmaf(p, vv.x, o[d].x);
                    o[d].y = fmaf(p, vv.y, o[d].y);
                    o[d].z = fmaf(p, vv.z, o[d].z);
                    o[d].w = fmaf(p, vv.w, o[d].w);
                }
            }
        }
    }

    float inv = 1.f / lrun;
    float4* op = reinterpret_cast<float4*>(O + base);
    #pragma unroll
    for (int i = 0; i < 8; i++)
        op[i] = make_float4(o[i].x * inv, o[i].y * inv, o[i].z * inv, o[i].w * inv);
}

// ---------------------------------------------------------------------------
// Launch: 5 kernels, graph-capturable, no allocations / syncs.
// ---------------------------------------------------------------------------
extern "C" void kernel_launch(void* const* d_in, const int* in_sizes, int n_in,
                              void* d_out, int out_size)
{
    const float* q    = (const float*)d_in[0];
    const float* k    = (const float*)d_in[1];
    const float* v    = (const float*)d_in[2];
    const int*   mask = (const int*)  d_in[3];
    const float* w_q  = (const float*)d_in[4];
    const float* w_k  = (const float*)d_in[5];
    const float* w_v  = (const float*)d_in[6];
    const float* w_o  = (const float*)d_in[7];
    float* out = (float*)d_out;

    float *gq, *gk, *gv, *ga;
    cudaGetSymbolAddress((void**)&gq, g_Q);
    cudaGetSymbolAddress((void**)&gk, g_K);
    cudaGetSymbolAddress((void**)&gv, g_V);
    cudaGetSymbolAddress((void**)&ga, g_A);

    const int M = B_ * S_;                 // 8192
    dim3 gemm_grid(D_ / 128, M / 128);     // (8, 64)

    gemm_atb_kernel<<<gemm_grid, 256>>>(q, w_q, gq, M, D_, D_);
    gemm_atb_kernel<<<gemm_grid, 256>>>(k, w_k, gk, M, D_, D_);
    gemm_atb_kernel<<<gemm_grid, 256>>>(v, w_v, gv, M, D_, D_);

    dim3 attn_grid(S_ / 128, B_ * H_);     // (16, 64)
    attn_kernel<<<attn_grid, 256>>>(gq, gk, gv, mask, ga);

    gemm_atb_kernel<<<gemm_grid, 256>>>(ga, w_o, out, M, D_, D_);
}